// round 1
// baseline (speedup 1.0000x reference)
#include <cuda_runtime.h>
#include <cuda_bf16.h>

#define NLVL 16
#define WIDTH 1000
#define A_CUBIC (-0.75f)

__device__ __forceinline__ float cubic_inner(float s) {
    // ((A+2)s - (A+3)) * s*s + 1  with A=-0.75 => (1.25 s - 2.25) s^2 + 1
    float p = fmaf(1.25f, s, -2.25f);
    return fmaf(p * s, s, 1.0f);
}
__device__ __forceinline__ float cubic_outer(float s) {
    // ((A s - 5A)s + 8A)s - 4A => ((-0.75 s + 3.75)s - 6)s + 3
    float p = fmaf(-0.75f, s, 3.75f);
    p = fmaf(p, s, -6.0f);
    return fmaf(p, s, 3.0f);
}

__global__ __launch_bounds__(1024, 1)
void trig_hash_kernel(const float* __restrict__ x,
                      const float* __restrict__ grids,
                      const float* __restrict__ G,
                      const float* __restrict__ H,
                      float2* __restrict__ out,
                      int n_items)
{
    extern __shared__ float2 gsm[];   // [NLVL * WIDTH], channels interleaved

    // Stage grids (N, C, W) -> smem [n][w] = {c0, c1}. Coalesced over w.
    for (int j = threadIdx.x; j < NLVL * WIDTH; j += blockDim.x) {
        int n = j / WIDTH;
        int w = j - n * WIDTH;
        float c0 = grids[(n * 2 + 0) * WIDTH + w];
        float c1 = grids[(n * 2 + 1) * WIDTH + w];
        gsm[j] = make_float2(c0, c1);
    }
    __syncthreads();

    const int gtid   = blockIdx.x * blockDim.x + threadIdx.x;
    const int stride = gridDim.x * blockDim.x;   // multiple of 16 -> n fixed per thread
    const int n = gtid & (NLVL - 1);

    // Per-level constants live in registers for the entire kernel.
    // G[d][m][n] at flat d*48 + m*16 + n ; H[m][n] at m*16 + n
    const float g00 = G[ 0 + n], g01 = G[16 + n], g02 = G[32 + n];   // d=0, m=0..2
    const float g10 = G[48 + n], g11 = G[64 + n], g12 = G[80 + n];   // d=1
    const float g20 = G[96 + n], g21 = G[112 + n], g22 = G[128 + n]; // d=2
    const float h0  = H[ 0 + n], h1  = H[16 + n], h2  = H[32 + n];

    const float2* __restrict__ gr = gsm + n * WIDTH;

    for (int i = gtid; i < n_items; i += stride) {
        const int s = i >> 4;
        const float x0 = x[3 * s + 0];
        const float x1 = x[3 * s + 1];
        const float x2 = x[3 * s + 2];

        float a0 = fmaf(x0, g00, fmaf(x1, g10, fmaf(x2, g20, h0)));
        float a1 = fmaf(x0, g01, fmaf(x1, g11, fmaf(x2, g21, h1)));
        float a2 = fmaf(x0, g02, fmaf(x1, g12, fmaf(x2, g22, h2)));

        float gx = sinf(a0) * sinf(a1) * sinf(a2);

        // ix = ((gx + 1) * W - 1) / 2   in [-0.5, 999.5]
        float ix = ((gx + 1.0f) * 1000.0f - 1.0f) * 0.5f;
        float xf = floorf(ix);
        float t  = ix - xf;
        int base = (int)xf;

        float wt0 = cubic_outer(t + 1.0f);
        float wt1 = cubic_inner(t);
        float wt2 = cubic_inner(1.0f - t);
        float wt3 = cubic_outer(2.0f - t);

        float acc0 = 0.0f, acc1 = 0.0f;
        {
            int idx = base - 1;
            float wk = ((unsigned)idx < (unsigned)WIDTH) ? wt0 : 0.0f;
            int ic = min(max(idx, 0), WIDTH - 1);
            float2 v = gr[ic];
            acc0 = fmaf(v.x, wk, acc0); acc1 = fmaf(v.y, wk, acc1);
        }
        {
            int idx = base;
            float wk = ((unsigned)idx < (unsigned)WIDTH) ? wt1 : 0.0f;
            int ic = min(max(idx, 0), WIDTH - 1);
            float2 v = gr[ic];
            acc0 = fmaf(v.x, wk, acc0); acc1 = fmaf(v.y, wk, acc1);
        }
        {
            int idx = base + 1;
            float wk = ((unsigned)idx < (unsigned)WIDTH) ? wt2 : 0.0f;
            int ic = min(max(idx, 0), WIDTH - 1);
            float2 v = gr[ic];
            acc0 = fmaf(v.x, wk, acc0); acc1 = fmaf(v.y, wk, acc1);
        }
        {
            int idx = base + 2;
            float wk = ((unsigned)idx < (unsigned)WIDTH) ? wt3 : 0.0f;
            int ic = min(max(idx, 0), WIDTH - 1);
            float2 v = gr[ic];
            acc0 = fmaf(v.x, wk, acc0); acc1 = fmaf(v.y, wk, acc1);
        }

        // out[s][n][c] flat = s*32 + n*2 + c  -> float2 index s*16 + n == i
        out[i] = make_float2(acc0, acc1);
    }
}

extern "C" void kernel_launch(void* const* d_in, const int* in_sizes, int n_in,
                              void* d_out, int out_size)
{
    const float* x     = (const float*)d_in[0];
    const float* grids = (const float*)d_in[1];
    const float* G     = (const float*)d_in[2];
    const float* H     = (const float*)d_in[3];
    (void)n_in;

    const int B = in_sizes[0] / 3;
    const int n_items = B * NLVL;

    const int smem_bytes = NLVL * WIDTH * (int)sizeof(float2);   // 128000

    cudaFuncSetAttribute(trig_hash_kernel,
                         cudaFuncAttributeMaxDynamicSharedMemorySize, smem_bytes);

    int sm_count = 148;
    cudaDeviceGetAttribute(&sm_count, cudaDevAttrMultiProcessorCount, 0);

    trig_hash_kernel<<<sm_count, 1024, smem_bytes>>>(
        x, grids, G, H, (float2*)d_out, n_items);
}

// round 2
// speedup vs baseline: 1.4645x; 1.4645x over previous
#include <cuda_runtime.h>

#define NLVL   16
#define WIDTH  1000
#define PADW   (WIDTH + 4)     // w in [-2, 1001]
#define TPB    768             // multiple of 16; reg cap 65536/768 = 85

typedef unsigned long long u64;
typedef unsigned int       u32;

// ---------------- packed f32x2 helpers ----------------
__device__ __forceinline__ u64 pk(float lo, float hi) {
    u64 r; asm("mov.b64 %0, {%1,%2};" : "=l"(r) : "f"(lo), "f"(hi)); return r;
}
__device__ __forceinline__ void upk(float& lo, float& hi, u64 v) {
    asm("mov.b64 {%0,%1}, %2;" : "=f"(lo), "=f"(hi) : "l"(v));
}
__device__ __forceinline__ u64 f2fma(u64 a, u64 b, u64 c) {
    u64 r; asm("fma.rn.f32x2 %0, %1, %2, %3;" : "=l"(r) : "l"(a), "l"(b), "l"(c)); return r;
}
__device__ __forceinline__ u64 f2mul(u64 a, u64 b) {
    u64 r; asm("mul.rn.f32x2 %0, %1, %2;" : "=l"(r) : "l"(a), "l"(b)); return r;
}
__device__ __forceinline__ u64 f2add(u64 a, u64 b) {
    u64 r; asm("add.rn.f32x2 %0, %1, %2;" : "=l"(r) : "l"(a), "l"(b)); return r;
}
__device__ __forceinline__ u64 f2sub(u64 a, u64 b) {
    u64 r; asm("sub.rn.f32x2 %0, %1, %2;" : "=l"(r) : "l"(a), "l"(b)); return r;
}
__device__ __forceinline__ u64 bc(float v) { return pk(v, v); }

// packed sin for two independent arguments (one lane-pair).
// 3-term Cody-Waite (all splits exact for |k| < 2^12) + degree-11 odd poly.
// Sign of (-1)^k is NOT applied here; the magic-biased k (integer bits in
// mantissa LSBs) is XORed into kacc so the caller can apply the product parity.
__device__ __forceinline__ u64 psin(u64 a, u64& kacc,
                                    u64 INVPI, u64 MAGIC,
                                    u64 PIA, u64 PIB, u64 PIC,
                                    u64 C3, u64 C5, u64 C7, u64 C9, u64 C11) {
    u64 kb = f2fma(a, INVPI, MAGIC);   // rint via magic; mantissa LSB = k&1
    kacc  ^= kb;
    u64 k  = f2sub(kb, MAGIC);
    u64 r  = f2fma(k, PIA, a);         // PIA = -3.140625          (exact step)
    r      = f2fma(k, PIB, r);         // PIB = -9.6702576e-4      (exact step)
    r      = f2fma(k, PIC, r);         // PIC = -6.2783296e-7      (1 rounding)
    u64 s  = f2mul(r, r);
    u64 p  = f2fma(C11, s, C9);
    p      = f2fma(p, s, C7);
    p      = f2fma(p, s, C5);
    p      = f2fma(p, s, C3);
    return f2fma(f2mul(p, s), r, r);   // |sin(r)|, sign applied by caller
}

__global__ __launch_bounds__(TPB, 1)
void trig_hash_kernel(const float* __restrict__ x,
                      const float* __restrict__ grids,
                      const float* __restrict__ G,
                      const float* __restrict__ H,
                      float2* __restrict__ out,
                      int n_pairs)     // (B/2)*16
{
    extern __shared__ float2 gsm[];    // [(w+2)*16 + n] : bank pair = 2n -> conflict-free

    // Stage grids (N,C,W) -> transposed padded smem. Zeros outside [0,W).
    for (int j = threadIdx.x; j < PADW * NLVL; j += TPB) {
        int n = j & (NLVL - 1);
        int w = (j >> 4) - 2;
        float c0 = 0.f, c1 = 0.f;
        if ((unsigned)w < (unsigned)WIDTH) {
            c0 = grids[(n * 2 + 0) * WIDTH + w];
            c1 = grids[(n * 2 + 1) * WIDTH + w];
        }
        gsm[j] = make_float2(c0, c1);
    }
    __syncthreads();

    const int gtid   = blockIdx.x * TPB + threadIdx.x;
    const int stride = gridDim.x * TPB;       // multiple of 16
    const int n      = gtid & (NLVL - 1);

    // Per-level constants, packed (same level for both samples of the pair).
    const u64 G00 = bc(G[  0 + n]), G01 = bc(G[ 16 + n]), G02 = bc(G[ 32 + n]);
    const u64 G10 = bc(G[ 48 + n]), G11 = bc(G[ 64 + n]), G12 = bc(G[ 80 + n]);
    const u64 G20 = bc(G[ 96 + n]), G21 = bc(G[112 + n]), G22 = bc(G[128 + n]);
    const u64 H0  = bc(H[  0 + n]), H1  = bc(H[ 16 + n]), H2  = bc(H[ 32 + n]);

    // Packed numeric constants (hoisted once).
    const u64 INVPI = bc(0.3183098861837907f);
    const u64 MAGIC = bc(12582912.0f);                 // 1.5 * 2^23
    const u64 PIA   = bc(-3.140625f);
    const u64 PIB   = bc(-9.670257568359375e-4f);
    const u64 PIC   = bc(-6.2783296e-7f);
    const u64 C3    = bc(-1.6666667e-1f);
    const u64 C5    = bc( 8.3333333e-3f);
    const u64 C7    = bc(-1.9841270e-4f);
    const u64 C9    = bc( 2.7557319e-6f);
    const u64 C11   = bc(-2.5052108e-8f);
    const u64 ONEp  = bc(1.0f);
    const u64 K1Kp  = bc(1000.0f);
    const u64 NEG1p = bc(-1.0f);
    const u64 HALFp = bc(0.5f);
    const u64 NHLFp = bc(-0.5f);

    // smem u32 base address for the LDS asm
    u32 smbase;
    asm("{ .reg .u64 t; cvta.to.shared.u64 t, %1; cvt.u32.u64 %0, t; }"
        : "=r"(smbase) : "l"(gsm));
    // addr(tap0,item) = bits(bbig)*128 + addrc    (wraps mod 2^32, fine)
    const u32 addrc = smbase + 128u + (u32)(n * 8) - 0xA0000000u; // 0x4B400000*128 mod 2^32

    for (int p = gtid; p < n_pairs; p += stride) {
        const int g = p >> 4;                 // samples 2g, 2g+1
        const float2* xp = (const float2*)(x + 6 * g);  // 24g bytes, 8B aligned
        float2 q0 = xp[0];                    // x0A x1A
        float2 q1 = xp[1];                    // x2A x0B
        float2 q2 = xp[2];                    // x1B x2B
        u64 X0 = pk(q0.x, q1.y);
        u64 X1 = pk(q0.y, q2.x);
        u64 X2 = pk(q1.x, q2.y);

        u64 a0 = f2fma(X0, G00, f2fma(X1, G10, f2fma(X2, G20, H0)));
        u64 a1 = f2fma(X0, G01, f2fma(X1, G11, f2fma(X2, G21, H1)));
        u64 a2 = f2fma(X0, G02, f2fma(X1, G12, f2fma(X2, G22, H2)));

        u64 kacc = 0;
        u64 s0 = psin(a0, kacc, INVPI, MAGIC, PIA, PIB, PIC, C3, C5, C7, C9, C11);
        u64 s1 = psin(a1, kacc, INVPI, MAGIC, PIA, PIB, PIC, C3, C5, C7, C9, C11);
        u64 s2 = psin(a2, kacc, INVPI, MAGIC, PIA, PIB, PIC, C3, C5, C7, C9, C11);
        u64 gx = f2mul(f2mul(s0, s1), s2);
        // apply product sign: parity of k0+k1+k2 per half
        gx ^= (kacc & 0x0000000100000001ULL) << 31;

        // ix chain, rounding-matched to reference: ((gx+1)*1000 - 1) * 0.5
        u64 t1  = f2add(gx, ONEp);
        u64 t2  = f2mul(t1, K1Kp);
        u64 t3  = f2add(t2, NEG1p);
        u64 ixm = f2fma(t3, HALFp, NHLFp);    // ix - 0.5  (exact given t3*0.5 exact)
        u64 bb  = f2add(ixm, MAGIC);          // MAGIC + floor(ix) in int bits
        u64 xf  = f2sub(bb, MAGIC);           // floor(ix) (rint ties benign: weights continuous)
        u64 xfn = xf ^ 0x8000000080000000ULL;
        u64 tp  = f2fma(t3, HALFp, xfn);      // t = ix - floor(ix), exact
        float tA, tB; upk(tA, tB, tp);

        const u32 bbA = (u32)bb, bbB = (u32)(bb >> 32);

        float accA0, accA1, accB0, accB1;
        // ---- item A (sample 2g) ----
        {
            float t = tA;
            float pa = fmaf(-0.75f, t, 1.5f);  pa = fmaf(pa, t, -0.75f);
            float w0 = pa * t;                                   // -0.75t^3+1.5t^2-0.75t
            float pb = fmaf(1.25f, t, -2.25f);
            float w1 = fmaf(pb * t, t, 1.0f);                    // 1.25t^3-2.25t^2+1
            float pc = fmaf(-1.25f, t, 1.5f);  pc = fmaf(pc, t, 0.75f);
            float w2 = pc * t;                                   // -1.25t^3+1.5t^2+0.75t
            float pd = fmaf(0.75f, t, -0.75f);
            float w3 = pd * t * t;                               // 0.75t^3-0.75t^2
            u32 ad = bbA * 128u + addrc;
            float v0x, v0y, v1x, v1y, v2x, v2y, v3x, v3y;
            asm("ld.shared.v2.f32 {%0,%1},[%2];"     : "=f"(v0x), "=f"(v0y) : "r"(ad));
            asm("ld.shared.v2.f32 {%0,%1},[%2+128];" : "=f"(v1x), "=f"(v1y) : "r"(ad));
            asm("ld.shared.v2.f32 {%0,%1},[%2+256];" : "=f"(v2x), "=f"(v2y) : "r"(ad));
            asm("ld.shared.v2.f32 {%0,%1},[%2+384];" : "=f"(v3x), "=f"(v3y) : "r"(ad));
            accA0 = fmaf(v0x, w0, fmaf(v1x, w1, fmaf(v2x, w2, v3x * w3)));
            accA1 = fmaf(v0y, w0, fmaf(v1y, w1, fmaf(v2y, w2, v3y * w3)));
        }
        // ---- item B (sample 2g+1) ----
        {
            float t = tB;
            float pa = fmaf(-0.75f, t, 1.5f);  pa = fmaf(pa, t, -0.75f);
            float w0 = pa * t;
            float pb = fmaf(1.25f, t, -2.25f);
            float w1 = fmaf(pb * t, t, 1.0f);
            float pc = fmaf(-1.25f, t, 1.5f);  pc = fmaf(pc, t, 0.75f);
            float w2 = pc * t;
            float pd = fmaf(0.75f, t, -0.75f);
            float w3 = pd * t * t;
            u32 ad = bbB * 128u + addrc;
            float v0x, v0y, v1x, v1y, v2x, v2y, v3x, v3y;
            asm("ld.shared.v2.f32 {%0,%1},[%2];"     : "=f"(v0x), "=f"(v0y) : "r"(ad));
            asm("ld.shared.v2.f32 {%0,%1},[%2+128];" : "=f"(v1x), "=f"(v1y) : "r"(ad));
            asm("ld.shared.v2.f32 {%0,%1},[%2+256];" : "=f"(v2x), "=f"(v2y) : "r"(ad));
            asm("ld.shared.v2.f32 {%0,%1},[%2+384];" : "=f"(v3x), "=f"(v3y) : "r"(ad));
            accB0 = fmaf(v0x, w0, fmaf(v1x, w1, fmaf(v2x, w2, v3x * w3)));
            accB1 = fmaf(v0y, w0, fmaf(v1y, w1, fmaf(v2y, w2, v3y * w3)));
        }

        // out float2 index = s*16 + n
        const int iA = (2 * g) * NLVL + n;
        out[iA]        = make_float2(accA0, accA1);
        out[iA + NLVL] = make_float2(accB0, accB1);
    }
}

extern "C" void kernel_launch(void* const* d_in, const int* in_sizes, int n_in,
                              void* d_out, int out_size)
{
    const float* x     = (const float*)d_in[0];
    const float* grids = (const float*)d_in[1];
    const float* G     = (const float*)d_in[2];
    const float* H     = (const float*)d_in[3];
    (void)n_in; (void)out_size;

    const int B       = in_sizes[0] / 3;      // 1048576 (even)
    const int n_pairs = (B / 2) * NLVL;

    const int smem_bytes = PADW * NLVL * (int)sizeof(float2);   // 128512

    cudaFuncSetAttribute(trig_hash_kernel,
                         cudaFuncAttributeMaxDynamicSharedMemorySize, smem_bytes);

    int sm_count = 148;
    cudaDeviceGetAttribute(&sm_count, cudaDevAttrMultiProcessorCount, 0);

    trig_hash_kernel<<<sm_count, TPB, smem_bytes>>>(
        x, grids, G, H, (float2*)d_out, n_pairs);
}

// round 3
// speedup vs baseline: 1.5152x; 1.0347x over previous
#include <cuda_runtime.h>

#define NLVL   16
#define WIDTH  1000
#define PADW   (WIDTH + 4)     // w in [-2, 1001]
#define TPB    1024            // 32 warps, reg cap 64

typedef unsigned long long u64;
typedef unsigned int       u32;

// ---------------- packed f32x2 helpers ----------------
__device__ __forceinline__ u64 pk(float lo, float hi) {
    u64 r; asm("mov.b64 %0, {%1,%2};" : "=l"(r) : "f"(lo), "f"(hi)); return r;
}
__device__ __forceinline__ void upk(float& lo, float& hi, u64 v) {
    asm("mov.b64 {%0,%1}, %2;" : "=f"(lo), "=f"(hi) : "l"(v));
}
__device__ __forceinline__ u64 f2fma(u64 a, u64 b, u64 c) {
    u64 r; asm("fma.rn.f32x2 %0, %1, %2, %3;" : "=l"(r) : "l"(a), "l"(b), "l"(c)); return r;
}
__device__ __forceinline__ u64 f2mul(u64 a, u64 b) {
    u64 r; asm("mul.rn.f32x2 %0, %1, %2;" : "=l"(r) : "l"(a), "l"(b)); return r;
}
__device__ __forceinline__ u64 f2add(u64 a, u64 b) {
    u64 r; asm("add.rn.f32x2 %0, %1, %2;" : "=l"(r) : "l"(a), "l"(b)); return r;
}
__device__ __forceinline__ u64 f2sub(u64 a, u64 b) {
    u64 r; asm("sub.rn.f32x2 %0, %1, %2;" : "=l"(r) : "l"(a), "l"(b)); return r;
}
__device__ __forceinline__ u64 bc(float v) { return pk(v, v); }

// packed sin for two independent arguments (one lane-pair).
// 3-term Cody-Waite (exact split steps) + degree-11 odd poly.
// (-1)^k sign NOT applied; magic-biased k bits XORed into kacc so the caller
// applies the 3-sin product parity once.
__device__ __forceinline__ u64 psin(u64 a, u64& kacc,
                                    u64 INVPI, u64 MAGIC,
                                    u64 PIA, u64 PIB, u64 PIC,
                                    u64 C3, u64 C5, u64 C7, u64 C9, u64 C11) {
    u64 kb = f2fma(a, INVPI, MAGIC);   // rint via magic; mantissa LSB = k&1
    kacc  ^= kb;
    u64 k  = f2sub(kb, MAGIC);
    u64 r  = f2fma(k, PIA, a);
    r      = f2fma(k, PIB, r);
    r      = f2fma(k, PIC, r);
    u64 s  = f2mul(r, r);
    u64 p  = f2fma(C11, s, C9);
    p      = f2fma(p, s, C7);
    p      = f2fma(p, s, C5);
    p      = f2fma(p, s, C3);
    return f2fma(f2mul(p, s), r, r);
}

__global__ __launch_bounds__(TPB, 1)
void trig_hash_kernel(const float* __restrict__ x,
                      const float* __restrict__ grids,
                      const float* __restrict__ G,
                      const float* __restrict__ H,
                      float2* __restrict__ out,
                      int n_pairs)     // (B/2)*16
{
    extern __shared__ float2 gsm[];    // [(w+2)*16 + n] : bank pair = 2n

    // Stage grids (N,C,W) -> transposed padded smem. Zeros outside [0,W).
    for (int j = threadIdx.x; j < PADW * NLVL; j += TPB) {
        int n = j & (NLVL - 1);
        int w = (j >> 4) - 2;
        float c0 = 0.f, c1 = 0.f;
        if ((unsigned)w < (unsigned)WIDTH) {
            c0 = grids[(n * 2 + 0) * WIDTH + w];
            c1 = grids[(n * 2 + 1) * WIDTH + w];
        }
        gsm[j] = make_float2(c0, c1);
    }
    __syncthreads();

    const int gtid   = blockIdx.x * TPB + threadIdx.x;
    const int stride = gridDim.x * TPB;       // multiple of 16
    const int n      = gtid & (NLVL - 1);

    // Per-level constants in registers for the whole kernel.
    const u64 G00 = bc(G[  0 + n]), G01 = bc(G[ 16 + n]), G02 = bc(G[ 32 + n]);
    const u64 G10 = bc(G[ 48 + n]), G11 = bc(G[ 64 + n]), G12 = bc(G[ 80 + n]);
    const u64 G20 = bc(G[ 96 + n]), G21 = bc(G[112 + n]), G22 = bc(G[128 + n]);
    const u64 H0  = bc(H[  0 + n]), H1  = bc(H[ 16 + n]), H2  = bc(H[ 32 + n]);

    // Packed numeric constants (uniform -> UR file).
    const u64 INVPI = bc(0.3183098861837907f);
    const u64 MAGIC = bc(12582912.0f);                 // 1.5 * 2^23
    const u64 PIA   = bc(-3.140625f);
    const u64 PIB   = bc(-9.670257568359375e-4f);
    const u64 PIC   = bc(-6.2783296e-7f);
    const u64 C3    = bc(-1.6666667e-1f);
    const u64 C5    = bc( 8.3333333e-3f);
    const u64 C7    = bc(-1.9841270e-4f);
    const u64 C9    = bc( 2.7557319e-6f);
    const u64 C11   = bc(-2.5052108e-8f);
    const u64 ONEp  = bc(1.0f);
    const u64 K1Kp  = bc(1000.0f);
    const u64 NEG1p = bc(-1.0f);
    const u64 HALFp = bc(0.5f);
    const u64 NHLFp = bc(-0.5f);
    const u64 Cm075 = bc(-0.75f);
    const u64 C15   = bc(1.5f);
    const u64 C125  = bc(1.25f);
    const u64 Cm225 = bc(-2.25f);
    const u64 Cm125 = bc(-1.25f);
    const u64 C075  = bc(0.75f);

    u32 smbase;
    asm("{ .reg .u64 t; cvta.to.shared.u64 t, %1; cvt.u32.u64 %0, t; }"
        : "=r"(smbase) : "l"(gsm));
    // addr(tap0) = bits(bb)*128 + addrc   (0x4B400000*128 mod 2^32 = 0xA0000000)
    const u32 addrc = smbase + 128u + (u32)(n * 8) - 0xA0000000u;

    for (int p = gtid; p < n_pairs; p += stride) {
        const int g = p >> 4;                 // samples 2g, 2g+1
        const float2* xp = (const float2*)(x + 6 * g);
        float2 q0 = xp[0];                    // x0A x1A
        float2 q1 = xp[1];                    // x2A x0B
        float2 q2 = xp[2];                    // x1B x2B
        u64 X0 = pk(q0.x, q1.y);
        u64 X1 = pk(q0.y, q2.x);
        u64 X2 = pk(q1.x, q2.y);

        u64 a0 = f2fma(X0, G00, f2fma(X1, G10, f2fma(X2, G20, H0)));
        u64 a1 = f2fma(X0, G01, f2fma(X1, G11, f2fma(X2, G21, H1)));
        u64 a2 = f2fma(X0, G02, f2fma(X1, G12, f2fma(X2, G22, H2)));

        u64 kacc = 0;
        u64 s0 = psin(a0, kacc, INVPI, MAGIC, PIA, PIB, PIC, C3, C5, C7, C9, C11);
        u64 s1 = psin(a1, kacc, INVPI, MAGIC, PIA, PIB, PIC, C3, C5, C7, C9, C11);
        u64 s2 = psin(a2, kacc, INVPI, MAGIC, PIA, PIB, PIC, C3, C5, C7, C9, C11);
        u64 gx = f2mul(f2mul(s0, s1), s2);
        gx ^= (kacc & 0x0000000100000001ULL) << 31;   // product parity sign

        // ix chain, rounding-matched to reference: ((gx+1)*1000 - 1) * 0.5
        u64 t1  = f2add(gx, ONEp);
        u64 t2  = f2mul(t1, K1Kp);
        u64 t3  = f2add(t2, NEG1p);
        u64 ixm = f2fma(t3, HALFp, NHLFp);    // ix - 0.5 (exact)
        u64 bb  = f2add(ixm, MAGIC);          // MAGIC + floor(ix), int bits in mantissa
        u64 xf  = f2sub(bb, MAGIC);           // floor(ix)
        u64 xfn = xf ^ 0x8000000080000000ULL;
        u64 tp  = f2fma(t3, HALFp, xfn);      // t = ix - floor(ix), exact
        const u32 bbA = (u32)bb, bbB = (u32)(bb >> 32);

        // ---- issue all 8 tap loads up front (overlap LDS latency with weights) ----
        const u32 adA = bbA * 128u + addrc;
        const u32 adB = bbB * 128u + addrc;
        float a0x,a0y,a1x,a1y,a2x,a2y,a3x,a3y;
        float b0x,b0y,b1x,b1y,b2x,b2y,b3x,b3y;
        asm("ld.shared.v2.f32 {%0,%1},[%2];"     : "=f"(a0x), "=f"(a0y) : "r"(adA));
        asm("ld.shared.v2.f32 {%0,%1},[%2+128];" : "=f"(a1x), "=f"(a1y) : "r"(adA));
        asm("ld.shared.v2.f32 {%0,%1},[%2+256];" : "=f"(a2x), "=f"(a2y) : "r"(adA));
        asm("ld.shared.v2.f32 {%0,%1},[%2+384];" : "=f"(a3x), "=f"(a3y) : "r"(adA));
        asm("ld.shared.v2.f32 {%0,%1},[%2];"     : "=f"(b0x), "=f"(b0y) : "r"(adB));
        asm("ld.shared.v2.f32 {%0,%1},[%2+128];" : "=f"(b1x), "=f"(b1y) : "r"(adB));
        asm("ld.shared.v2.f32 {%0,%1},[%2+256];" : "=f"(b2x), "=f"(b2y) : "r"(adB));
        asm("ld.shared.v2.f32 {%0,%1},[%2+384];" : "=f"(b3x), "=f"(b3y) : "r"(adB));

        // ---- packed cubic-convolution weights (A in lo, B in hi) ----
        // w0 = ((-0.75t+1.5)t-0.75)t ; w1 = (1.25t-2.25)t^2+1
        // w2 = ((-1.25t+1.5)t+0.75)t ; w3 = (0.75t-0.75)t^2
        u64 pa = f2fma(Cm075, tp, C15);  pa = f2fma(pa, tp, Cm075);
        u64 W0 = f2mul(pa, tp);
        u64 pb = f2fma(C125, tp, Cm225);
        u64 W1 = f2fma(f2mul(pb, tp), tp, ONEp);
        u64 pc = f2fma(Cm125, tp, C15);  pc = f2fma(pc, tp, C075);
        u64 W2 = f2mul(pc, tp);
        u64 pd = f2fma(C075, tp, Cm075);
        u64 W3 = f2mul(f2mul(pd, tp), tp);

        float w0A,w0B,w1A,w1B,w2A,w2B,w3A,w3B;
        upk(w0A, w0B, W0); upk(w1A, w1B, W1);
        upk(w2A, w2B, W2); upk(w3A, w3B, W3);

        float accA0 = fmaf(a0x, w0A, fmaf(a1x, w1A, fmaf(a2x, w2A, a3x * w3A)));
        float accA1 = fmaf(a0y, w0A, fmaf(a1y, w1A, fmaf(a2y, w2A, a3y * w3A)));
        float accB0 = fmaf(b0x, w0B, fmaf(b1x, w1B, fmaf(b2x, w2B, b3x * w3B)));
        float accB1 = fmaf(b0y, w0B, fmaf(b1y, w1B, fmaf(b2y, w2B, b3y * w3B)));

        const int iA = (2 * g) * NLVL + n;    // out float2 index = s*16 + n
        out[iA]        = make_float2(accA0, accA1);
        out[iA + NLVL] = make_float2(accB0, accB1);
    }
}

extern "C" void kernel_launch(void* const* d_in, const int* in_sizes, int n_in,
                              void* d_out, int out_size)
{
    const float* x     = (const float*)d_in[0];
    const float* grids = (const float*)d_in[1];
    const float* G     = (const float*)d_in[2];
    const float* H     = (const float*)d_in[3];
    (void)n_in; (void)out_size;

    const int B       = in_sizes[0] / 3;
    const int n_pairs = (B / 2) * NLVL;

    const int smem_bytes = PADW * NLVL * (int)sizeof(float2);   // 128512

    cudaFuncSetAttribute(trig_hash_kernel,
                         cudaFuncAttributeMaxDynamicSharedMemorySize, smem_bytes);

    int sm_count = 148;
    cudaDeviceGetAttribute(&sm_count, cudaDevAttrMultiProcessorCount, 0);

    trig_hash_kernel<<<sm_count, TPB, smem_bytes>>>(
        x, grids, G, H, (float2*)d_out, n_pairs);
}